// round 16
// baseline (speedup 1.0000x reference)
#include <cuda_runtime.h>
#include <cuda_fp16.h>

// MMDLoss: hard-negative selection + RBF MMD, sm_103a (compute_103 PTX -> no tcgen05).
// R15 bodies. Mega kernel with DISPATCH-ORDERED overlap (fixes R14):
//   bids [0,136)      : X-X gram tiles (no Y dep) -- overlap gather
//   bids [136,1160)   : gather CTAs (bump g_gdone)
//   bids [1160,1552)  : Y-dependent gram tiles (spin on g_gdone)

#define GAMMA_F 0.00065f

constexpr int C_  = 768;
constexpr int N_  = 2048;
constexpr int NZ  = 4096;
constexpr int K_  = 768;

__device__ __half   g_Zh[NZ * K_];   // fp16 rows: X then Ysel
__device__ float    g_sq[NZ];        // sqnorms of fp16-rounded rows (atomic-built)
__device__ float    g_D2[N_ * 16];   // selection d2 per (n, candidate), atomic-built
__device__ double   g_acc[3];
__device__ unsigned g_cnt;
__device__ unsigned g_gdone;

// ---------------------------------------------------------------------------
// 0) Zero accumulators + sqnorms + d2 + flags
// ---------------------------------------------------------------------------
__global__ void zero_kernel() {
  int t = blockIdx.x * 256 + threadIdx.x;   // 0..2047
  g_sq[t]        = 0.f;
  g_sq[t + 2048] = 0.f;
#pragma unroll
  for (int k = 0; k < 16; ++k) g_D2[t * 16 + k] = 0.f;
  if (t < 3) g_acc[t] = 0.0;
  if (t == 3) g_cnt = 0u;
  if (t == 4) g_gdone = 0u;
}

// ---------------------------------------------------------------------------
// 1) d2 + X-row emission (R15-proven). block=(b,h1,chunk of 48 c), 128 thr.
// ---------------------------------------------------------------------------
__global__ void d2_kernel(const float* __restrict__ x, const float* __restrict__ y) {
  __shared__ float Zs[32][49];
  __shared__ float sqp[4][32];
  int bid = blockIdx.x;
  int chunk = bid & 15, h1 = (bid >> 4) & 31, b = bid >> 9;
  int t = threadIdx.x, r = t >> 5, w1 = t & 31;
  int n0 = (b * 32 + h1) * 32;
  int c0 = chunk * 48;

  float s = 0.f;
#pragma unroll
  for (int i = 0; i < 12; ++i) {
    int cl = r + 4 * i;
    float v = x[(size_t)(b * C_ + c0 + cl) * 1024 + h1 * 32 + w1];
    float vr = __half2float(__float2half_rn(v));
    Zs[w1][cl] = vr;
    s = fmaf(vr, vr, s);
  }
  sqp[r][w1] = s;
  __syncthreads();
  if (t < 32) {
    float tt = (sqp[0][t] + sqp[1][t]) + (sqp[2][t] + sqp[3][t]);
    atomicAdd(&g_sq[n0 + t], tt);
  }
  {
    int row = t >> 2, g = t & 3;
    __half2 hb[6];
#pragma unroll
    for (int i = 0; i < 6; ++i)
      hb[i] = __floats2half2_rn(Zs[row][g * 12 + 2 * i], Zs[row][g * 12 + 2 * i + 1]);
    uint2* dst = (uint2*)(g_Zh + (size_t)(n0 + row) * K_ + c0 + g * 12);
    dst[0] = make_uint2(*(unsigned*)&hb[0], *(unsigned*)&hb[1]);
    dst[1] = make_uint2(*(unsigned*)&hb[2], *(unsigned*)&hb[3]);
    dst[2] = make_uint2(*(unsigned*)&hb[4], *(unsigned*)&hb[5]);
  }

  const float* yp = y + (size_t)(b * C_ + c0) * 16384 + (h1 * 4 + r) * 128 + w1 * 4;
  float a0 = 0.f, a1 = 0.f, a2 = 0.f, a3 = 0.f;
#pragma unroll 4
  for (int c = 0; c < 48; ++c) {
    float4 v = *(const float4*)(yp + (size_t)c * 16384);
    float z = Zs[w1][c];
    float d0 = z - v.x, d1 = z - v.y, d2 = z - v.z, d3 = z - v.w;
    a0 = fmaf(d0, d0, a0); a1 = fmaf(d1, d1, a1);
    a2 = fmaf(d2, d2, a2); a3 = fmaf(d3, d3, a3);
  }
  float* dst = g_D2 + (size_t)(n0 + w1) * 16 + r * 4;
  atomicAdd(dst + 0, a0);
  atomicAdd(dst + 1, a1);
  atomicAdd(dst + 2, a2);
  atomicAdd(dst + 3, a3);
}

// ---------------------------------------------------------------------------
// 2) Mega kernel: X-X tiles, then gather CTAs, then Y tiles.
// ---------------------------------------------------------------------------
__device__ __forceinline__ float pick4(float4 v, int jw) {
  return (jw & 2) ? ((jw & 1) ? v.w : v.z) : ((jw & 1) ? v.y : v.x);
}
__device__ __forceinline__ int swz(int row, int chunk) {
  return row * 64 + ((chunk ^ ((row >> 1) & 3)) << 4);
}
__device__ __forceinline__ unsigned smem_u32(const void* p) {
  unsigned a;
  asm("{ .reg .u64 t; cvta.to.shared.u64 t, %1; cvt.u32.u64 %0, t; }" : "=r"(a) : "l"(p));
  return a;
}
__device__ __forceinline__ void cpa16(unsigned dst, const void* src) {
  asm volatile("cp.async.cg.shared.global [%0], [%1], 16;" :: "r"(dst), "l"(src) : "memory");
}
__device__ __forceinline__ void ldsm4(unsigned* r, unsigned addr) {
  asm volatile("ldmatrix.sync.aligned.m8n8.x4.shared.b16 {%0,%1,%2,%3}, [%4];"
               : "=r"(r[0]), "=r"(r[1]), "=r"(r[2]), "=r"(r[3]) : "r"(addr));
}
__device__ __forceinline__ void mma16816(float* c, const unsigned* a, const unsigned* b) {
  asm volatile("mma.sync.aligned.m16n8k16.row.col.f32.f16.f16.f32 "
               "{%0,%1,%2,%3}, {%4,%5,%6,%7}, {%8,%9}, {%0,%1,%2,%3};"
               : "+f"(c[0]), "+f"(c[1]), "+f"(c[2]), "+f"(c[3])
               : "r"(a[0]), "r"(a[1]), "r"(a[2]), "r"(a[3]), "r"(b[0]), "r"(b[1]));
}

constexpr int NCHUNK  = 24;     // 768 / 32
constexpr int NXX     = 136;    // X-X tiles (br<16)
constexpr int NGATHER = 1024;   // gather CTAs
constexpr int GA0     = NXX;            // gather bid range start
constexpr int YT0     = NXX + NGATHER;  // Y-tile bid range start

__global__ void __launch_bounds__(256, 2) mega_kernel(const float* __restrict__ y,
                                                      float* __restrict__ out) {
  __shared__ __align__(16) char As[3][8192];
  __shared__ __align__(16) char Bs2[3][8192];
  __shared__ float red[8];
  __shared__ int jsh[32];
  __shared__ float sqp[8][32];

  int tid = threadIdx.x, lane = tid & 31, w = tid >> 5;

  // ========================== GATHER PATH ==========================
  if (blockIdx.x >= GA0 && blockIdx.x < YT0) {
    int gb = blockIdx.x - GA0;
    int chunk = gb & 15, h1 = (gb >> 4) & 31, b = gb >> 9;
    int w1 = tid & 31, cg = tid >> 5;        // cg: 0..7, 6 c's each
    int n0 = (b * 32 + h1) * 32;

    if (tid < 32) {
      const float* p = g_D2 + (size_t)(n0 + tid) * 16;
      float best = p[0]; int bi = 0;
#pragma unroll
      for (int j = 1; j < 16; ++j) {
        float v = p[j];
        if (v > best) { best = v; bi = j; }
      }
      jsh[tid] = bi;
    }
    __syncthreads();

    int n = n0 + w1;
    int j = jsh[w1], jh = j >> 2, jw = j & 3;
    int c0 = chunk * 48 + cg * 6;
    const float* yp = y + (size_t)(b * C_ + c0) * 16384 + (h1 * 4 + jh) * 128 + w1 * 4;
    float4 v0 = *(const float4*)(yp);
    float4 v1 = *(const float4*)(yp + (size_t)1 * 16384);
    float4 v2 = *(const float4*)(yp + (size_t)2 * 16384);
    float4 v3 = *(const float4*)(yp + (size_t)3 * 16384);
    float4 v4 = *(const float4*)(yp + (size_t)4 * 16384);
    float4 v5 = *(const float4*)(yp + (size_t)5 * 16384);
    __half2 q01 = __floats2half2_rn(pick4(v0, jw), pick4(v1, jw));
    __half2 q23 = __floats2half2_rn(pick4(v2, jw), pick4(v3, jw));
    __half2 q45 = __floats2half2_rn(pick4(v4, jw), pick4(v5, jw));
    unsigned* dst = (unsigned*)(g_Zh + (size_t)(N_ + n) * K_ + c0);
    dst[0] = *(unsigned*)&q01;
    dst[1] = *(unsigned*)&q23;
    dst[2] = *(unsigned*)&q45;
    float2 f0 = __half22float2(q01), f1 = __half22float2(q23), f2 = __half22float2(q45);
    float s = fmaf(f0.x, f0.x, f0.y * f0.y) + fmaf(f1.x, f1.x, f1.y * f1.y)
            + fmaf(f2.x, f2.x, f2.y * f2.y);

    sqp[cg][w1] = s;
    __syncthreads();
    if (tid < 32) {
      float tt = ((sqp[0][tid] + sqp[1][tid]) + (sqp[2][tid] + sqp[3][tid]))
               + ((sqp[4][tid] + sqp[5][tid]) + (sqp[6][tid] + sqp[7][tid]));
      atomicAdd(&g_sq[N_ + n0 + tid], tt);
    }
    __syncthreads();
    if (tid == 0) {
      __threadfence();
      atomicAdd(&g_gdone, 1u);
    }
    return;
  }

  // =========================== GRAM PATH ===========================
  int bid = (blockIdx.x < GA0) ? blockIdx.x : (blockIdx.x - NGATHER);  // 0..527
  int wm = w & 3, wn = w >> 2;
  int br = (int)((sqrtf(8.f * (float)bid + 1.f) - 1.f) * 0.5f);
  while ((br + 1) * (br + 2) / 2 <= bid) br++;
  while (br * (br + 1) / 2 > bid) br--;
  int bc = bid - br * (br + 1) / 2;
  bool diag = (br == bc);
  int i0 = br * 128, j0 = bc * 128;
  int cls = (br < 16) ? 0 : ((bc < 16) ? 1 : 2);

  if (cls != 0) {                      // Y rows needed -> wait for gather
    if (tid == 0) {
      unsigned v;
      do {
        asm volatile("ld.global.acquire.gpu.u32 %0, [%1];"
                     : "=r"(v) : "l"(&g_gdone) : "memory");
        if (v < (unsigned)NGATHER) __nanosleep(256);
      } while (v < (unsigned)NGATHER);
    }
    __syncthreads();
    __threadfence();
  }

  int lrow = tid >> 1, hb = tid & 1, cb = hb * 2;
  const __half* gA = g_Zh + (size_t)(i0 + lrow) * K_ + hb * 16;
  const __half* gB = g_Zh + (size_t)(j0 + lrow) * K_ + hb * 16;

  unsigned aAddr[3], bAddr[3];
#pragma unroll
  for (int s3 = 0; s3 < 3; ++s3) {
    aAddr[s3] = smem_u32(As[s3]);
    bAddr[s3] = smem_u32(Bs2[s3]);
  }

  auto issue = [&](int cn) {
    int bf = cn % 3;
    const __half* sa = gA + cn * 32;
    cpa16(aAddr[bf] + swz(lrow, cb),     sa);
    cpa16(aAddr[bf] + swz(lrow, cb + 1), sa + 8);
    if (!diag) {
      const __half* sb = gB + cn * 32;
      cpa16(bAddr[bf] + swz(lrow, cb),     sb);
      cpa16(bAddr[bf] + swz(lrow, cb + 1), sb + 8);
    }
    asm volatile("cp.async.commit_group;" ::: "memory");
  };

  int a_row = wm * 32 + (lane & 7) + ((lane >> 3) & 1) * 8;
  int a_chv = lane >> 4;
  int b_row = wn * 64 + (lane & 7) + (lane >> 4) * 8;
  int b_chv = (lane >> 3) & 1;

  float acc[2][8][4];
#pragma unroll
  for (int mt = 0; mt < 2; ++mt)
#pragma unroll
    for (int nt = 0; nt < 8; ++nt)
#pragma unroll
      for (int q = 0; q < 4; ++q) acc[mt][nt][q] = 0.f;

  issue(0);
  issue(1);

#pragma unroll 1
  for (int cn = 0; cn < NCHUNK; ++cn) {
    if (cn < NCHUNK - 2) asm volatile("cp.async.wait_group 1;" ::: "memory");
    else                 asm volatile("cp.async.wait_group 0;" ::: "memory");
    __syncthreads();
    if (cn + 2 < NCHUNK) issue(cn + 2);

    int bf = cn % 3;
    unsigned abase = aAddr[bf];
    unsigned bbase = diag ? aAddr[bf] : bAddr[bf];
#pragma unroll
    for (int ks = 0; ks < 2; ++ks) {
      unsigned afr[2][4];
#pragma unroll
      for (int mt = 0; mt < 2; ++mt)
        ldsm4(afr[mt], abase + swz(a_row + mt * 16, ks * 2 + a_chv));
      unsigned bfr[8][2];
#pragma unroll
      for (int p = 0; p < 4; ++p) {
        unsigned r4[4];
        ldsm4(r4, bbase + swz(b_row + p * 16, ks * 2 + b_chv));
        bfr[2 * p][0] = r4[0];     bfr[2 * p][1] = r4[1];
        bfr[2 * p + 1][0] = r4[2]; bfr[2 * p + 1][1] = r4[3];
      }
#pragma unroll
      for (int mt = 0; mt < 2; ++mt)
#pragma unroll
        for (int nt = 0; nt < 8; ++nt)
          mma16816(acc[mt][nt], afr[mt], bfr[nt]);
    }
  }

  // epilogue: dist -> exp -> masked accumulate
  int g = lane >> 2, qp = 2 * (lane & 3);
  float lsum = 0.f;
#pragma unroll
  for (int mt = 0; mt < 2; ++mt) {
    int ia = i0 + wm * 32 + mt * 16 + g;
    int ib = ia + 8;
    float sqa = g_sq[ia], sqb = g_sq[ib];
#pragma unroll
    for (int nt = 0; nt < 8; ++nt) {
      int jb0 = j0 + wn * 64 + nt * 8 + qp;
      float sj0 = g_sq[jb0], sj1 = g_sq[jb0 + 1];
      float d00 = fmaxf(sqa + sj0 - 2.f * acc[mt][nt][0], 0.f);
      float d01 = fmaxf(sqa + sj1 - 2.f * acc[mt][nt][1], 0.f);
      float d10 = fmaxf(sqb + sj0 - 2.f * acc[mt][nt][2], 0.f);
      float d11 = fmaxf(sqb + sj1 - 2.f * acc[mt][nt][3], 0.f);
      float e00 = __expf(-GAMMA_F * d00);
      float e01 = __expf(-GAMMA_F * d01);
      float e10 = __expf(-GAMMA_F * d10);
      float e11 = __expf(-GAMMA_F * d11);
      if (!diag) {
        lsum += (e00 + e01) + (e10 + e11);
      } else {
        if (jb0     < ia) lsum += e00;
        if (jb0 + 1 < ia) lsum += e01;
        if (jb0     < ib) lsum += e10;
        if (jb0 + 1 < ib) lsum += e11;
      }
    }
  }

  for (int off = 16; off; off >>= 1) lsum += __shfl_down_sync(0xffffffffu, lsum, off);
  if (lane == 0) red[w] = lsum;
  __syncthreads();
  if (tid == 0) {
    float s = 0.f;
#pragma unroll
    for (int k = 0; k < 8; ++k) s += red[k];
    atomicAdd(&g_acc[cls], (double)s);
    __threadfence();
    unsigned old = atomicAdd(&g_cnt, 1u);
    if (old == 527u) {
      volatile double* a = g_acc;
      double sxx = 2.0 * a[0] + (double)N_;
      double syy = 2.0 * a[2] + (double)N_;
      double sxy = a[1];
      out[0] = (float)((sxx + syy - 2.0 * sxy) / ((double)N_ * (double)N_));
    }
  }
}

extern "C" void kernel_launch(void* const* d_in, const int* in_sizes, int n_in,
                              void* d_out, int out_size) {
  const float* x = (const float*)d_in[0];
  const float* y = (const float*)d_in[1];

  zero_kernel<<<8, 256>>>();
  d2_kernel<<<1024, 128>>>(x, y);
  mega_kernel<<<NXX + NGATHER + 392, 256>>>(y, (float*)d_out);
}

// round 17
// speedup vs baseline: 1.2525x; 1.2525x over previous
#include <cuda_runtime.h>
#include <cuda_fp16.h>

// MMDLoss: hard-negative selection + RBF MMD, sm_103a (compute_103 PTX -> no tcgen05).
// R15 configuration (best: 86.5us) with a wide one-store-per-thread zero kernel
// (R16 profile showed the old zero at 5.5us, latency-bound at grid=8).
// Overlap is dead: three attempts (PDL, 2x mega) all lost to lean serial phases.

#define GAMMA_F 0.00065f

constexpr int C_  = 768;
constexpr int N_  = 2048;
constexpr int NZ  = 4096;
constexpr int K_  = 768;

__device__ __half   g_Zh[NZ * K_];   // fp16 rows: X then Ysel
__device__ float    g_sq[NZ];        // sqnorms of fp16-rounded rows (atomic-built)
__device__ float    g_D2[N_ * 16];   // selection d2 per (n, candidate), atomic-built
__device__ double   g_acc[3];
__device__ unsigned g_cnt;

// ---------------------------------------------------------------------------
// 0) Zero: one 4B store per thread (grid 72 x 512 = 36864 threads)
// ---------------------------------------------------------------------------
__global__ void zero_kernel() {
  int t = blockIdx.x * 512 + threadIdx.x;    // 0..36863
  if (t < N_ * 16) {
    g_D2[t] = 0.f;
  } else {
    int u = t - N_ * 16;                     // 0..4095
    if (u < NZ) g_sq[u] = 0.f;
  }
  if (blockIdx.x == 0) {
    if (threadIdx.x < 3) g_acc[threadIdx.x] = 0.0;
    if (threadIdx.x == 3) g_cnt = 0u;
  }
}

// ---------------------------------------------------------------------------
// 1) d2 + X-row emission (R15-proven). block=(b,h1,chunk of 48 c), 128 thr.
//    Phase A: load x slice directly (coalesced), round to fp16, stage Zs,
//             sqnorm partials, write fp16 X rows.
//    Phase B: selection d2 (float4 along w covers the 4 jw candidates).
// ---------------------------------------------------------------------------
__global__ void d2_kernel(const float* __restrict__ x, const float* __restrict__ y) {
  __shared__ float Zs[32][49];
  __shared__ float sqp[4][32];
  int bid = blockIdx.x;
  int chunk = bid & 15, h1 = (bid >> 4) & 31, b = bid >> 9;
  int t = threadIdx.x, r = t >> 5, w1 = t & 31;
  int n0 = (b * 32 + h1) * 32;
  int c0 = chunk * 48;

  float s = 0.f;
#pragma unroll
  for (int i = 0; i < 12; ++i) {
    int cl = r + 4 * i;
    float v = x[(size_t)(b * C_ + c0 + cl) * 1024 + h1 * 32 + w1];
    float vr = __half2float(__float2half_rn(v));
    Zs[w1][cl] = vr;
    s = fmaf(vr, vr, s);
  }
  sqp[r][w1] = s;
  __syncthreads();
  if (t < 32) {
    float tt = (sqp[0][t] + sqp[1][t]) + (sqp[2][t] + sqp[3][t]);
    atomicAdd(&g_sq[n0 + t], tt);
  }
  {
    int row = t >> 2, g = t & 3;
    __half2 hb[6];
#pragma unroll
    for (int i = 0; i < 6; ++i)
      hb[i] = __floats2half2_rn(Zs[row][g * 12 + 2 * i], Zs[row][g * 12 + 2 * i + 1]);
    uint2* dst = (uint2*)(g_Zh + (size_t)(n0 + row) * K_ + c0 + g * 12);
    dst[0] = make_uint2(*(unsigned*)&hb[0], *(unsigned*)&hb[1]);
    dst[1] = make_uint2(*(unsigned*)&hb[2], *(unsigned*)&hb[3]);
    dst[2] = make_uint2(*(unsigned*)&hb[4], *(unsigned*)&hb[5]);
  }

  const float* yp = y + (size_t)(b * C_ + c0) * 16384 + (h1 * 4 + r) * 128 + w1 * 4;
  float a0 = 0.f, a1 = 0.f, a2 = 0.f, a3 = 0.f;
#pragma unroll 4
  for (int c = 0; c < 48; ++c) {
    float4 v = *(const float4*)(yp + (size_t)c * 16384);
    float z = Zs[w1][c];
    float d0 = z - v.x, d1 = z - v.y, d2 = z - v.z, d3 = z - v.w;
    a0 = fmaf(d0, d0, a0); a1 = fmaf(d1, d1, a1);
    a2 = fmaf(d2, d2, a2); a3 = fmaf(d3, d3, a3);
  }
  float* dst = g_D2 + (size_t)(n0 + w1) * 16 + r * 4;
  atomicAdd(dst + 0, a0);
  atomicAdd(dst + 1, a1);
  atomicAdd(dst + 2, a2);
  atomicAdd(dst + 3, a3);
}

// ---------------------------------------------------------------------------
// 2) Gather with fused argmax (first-max strict-> scan = jnp tie rule).
//    grid 1024 (b,h1,c-chunk of 48), 128 threads, 12 c's per thread (MLP 12).
// ---------------------------------------------------------------------------
__device__ __forceinline__ float pick4(float4 v, int jw) {
  return (jw & 2) ? ((jw & 1) ? v.w : v.z) : ((jw & 1) ? v.y : v.x);
}

__global__ void gather_kernel(const float* __restrict__ y) {
  __shared__ int jsh[32];
  __shared__ float sqp[4][32];
  int bid = blockIdx.x;
  int chunk = bid & 15, h1 = (bid >> 4) & 31, b = bid >> 9;
  int t = threadIdx.x, w1 = t & 31, cg = t >> 5;
  int n0 = (b * 32 + h1) * 32;

  if (t < 32) {
    const float* p = g_D2 + (size_t)(n0 + t) * 16;
    float best = p[0]; int bi = 0;
#pragma unroll
    for (int j = 1; j < 16; ++j) {
      float v = p[j];
      if (v > best) { best = v; bi = j; }
    }
    jsh[t] = bi;
  }
  __syncthreads();

  int n = n0 + w1;
  int j = jsh[w1], jh = j >> 2, jw = j & 3;
  int c0 = chunk * 48 + cg * 12;
  const float* yp = y + (size_t)(b * C_ + c0) * 16384 + (h1 * 4 + jh) * 128 + w1 * 4;
  float s = 0.f;
  unsigned u[6];
#pragma unroll
  for (int i = 0; i < 6; ++i) {
    float4 v0 = *(const float4*)(yp + (size_t)(2 * i)     * 16384);
    float4 v1 = *(const float4*)(yp + (size_t)(2 * i + 1) * 16384);
    float p0 = pick4(v0, jw), p1 = pick4(v1, jw);
    __half2 hh = __floats2half2_rn(p0, p1);
    u[i] = *(unsigned*)&hh;
    float2 f2 = __half22float2(hh);
    s = fmaf(f2.x, f2.x, fmaf(f2.y, f2.y, s));
  }
  uint2* dst = (uint2*)(g_Zh + (size_t)(N_ + n) * K_ + c0);
  dst[0] = make_uint2(u[0], u[1]);
  dst[1] = make_uint2(u[2], u[3]);
  dst[2] = make_uint2(u[4], u[5]);

  sqp[cg][w1] = s;
  __syncthreads();
  if (t < 32) {
    float tt = (sqp[0][t] + sqp[1][t]) + (sqp[2][t] + sqp[3][t]);
    atomicAdd(&g_sq[N_ + n0 + t], tt);
  }
}

// ---------------------------------------------------------------------------
// 3) Tensor-core gram (proven): fp16 m16n8k16, BK=32, 3-stage cp.async,
//    fused dist->exp->masked-sum epilogue + device-side finalize.
// ---------------------------------------------------------------------------
__device__ __forceinline__ int swz(int row, int chunk) {
  return row * 64 + ((chunk ^ ((row >> 1) & 3)) << 4);
}
__device__ __forceinline__ unsigned smem_u32(const void* p) {
  unsigned a;
  asm("{ .reg .u64 t; cvta.to.shared.u64 t, %1; cvt.u32.u64 %0, t; }" : "=r"(a) : "l"(p));
  return a;
}
__device__ __forceinline__ void cpa16(unsigned dst, const void* src) {
  asm volatile("cp.async.cg.shared.global [%0], [%1], 16;" :: "r"(dst), "l"(src) : "memory");
}
__device__ __forceinline__ void ldsm4(unsigned* r, unsigned addr) {
  asm volatile("ldmatrix.sync.aligned.m8n8.x4.shared.b16 {%0,%1,%2,%3}, [%4];"
               : "=r"(r[0]), "=r"(r[1]), "=r"(r[2]), "=r"(r[3]) : "r"(addr));
}
__device__ __forceinline__ void mma16816(float* c, const unsigned* a, const unsigned* b) {
  asm volatile("mma.sync.aligned.m16n8k16.row.col.f32.f16.f16.f32 "
               "{%0,%1,%2,%3}, {%4,%5,%6,%7}, {%8,%9}, {%0,%1,%2,%3};"
               : "+f"(c[0]), "+f"(c[1]), "+f"(c[2]), "+f"(c[3])
               : "r"(a[0]), "r"(a[1]), "r"(a[2]), "r"(a[3]), "r"(b[0]), "r"(b[1]));
}

constexpr int NCHUNK = 24;   // 768 / 32

__global__ void __launch_bounds__(256, 2) gram_mma_kernel(float* __restrict__ out) {
  __shared__ __align__(16) char As[3][8192];
  __shared__ __align__(16) char Bs2[3][8192];
  __shared__ float red[8];

  int tid = threadIdx.x, lane = tid & 31, w = tid >> 5;
  int wm = w & 3, wn = w >> 2;

  int bid = blockIdx.x;
  int br = (int)((sqrtf(8.f * (float)bid + 1.f) - 1.f) * 0.5f);
  while ((br + 1) * (br + 2) / 2 <= bid) br++;
  while (br * (br + 1) / 2 > bid) br--;
  int bc = bid - br * (br + 1) / 2;
  bool diag = (br == bc);
  int i0 = br * 128, j0 = bc * 128;
  int cls = (br < 16) ? 0 : ((bc < 16) ? 1 : 2);

  int lrow = tid >> 1, hb = tid & 1, cb = hb * 2;
  const __half* gA = g_Zh + (size_t)(i0 + lrow) * K_ + hb * 16;
  const __half* gB = g_Zh + (size_t)(j0 + lrow) * K_ + hb * 16;

  unsigned aAddr[3], bAddr[3];
#pragma unroll
  for (int s3 = 0; s3 < 3; ++s3) {
    aAddr[s3] = smem_u32(As[s3]);
    bAddr[s3] = smem_u32(Bs2[s3]);
  }

  auto issue = [&](int cn) {
    int bf = cn % 3;
    const __half* sa = gA + cn * 32;
    cpa16(aAddr[bf] + swz(lrow, cb),     sa);
    cpa16(aAddr[bf] + swz(lrow, cb + 1), sa + 8);
    if (!diag) {
      const __half* sb = gB + cn * 32;
      cpa16(bAddr[bf] + swz(lrow, cb),     sb);
      cpa16(bAddr[bf] + swz(lrow, cb + 1), sb + 8);
    }
    asm volatile("cp.async.commit_group;" ::: "memory");
  };

  int a_row = wm * 32 + (lane & 7) + ((lane >> 3) & 1) * 8;
  int a_chv = lane >> 4;
  int b_row = wn * 64 + (lane & 7) + (lane >> 4) * 8;
  int b_chv = (lane >> 3) & 1;

  float acc[2][8][4];
#pragma unroll
  for (int mt = 0; mt < 2; ++mt)
#pragma unroll
    for (int nt = 0; nt < 8; ++nt)
#pragma unroll
      for (int q = 0; q < 4; ++q) acc[mt][nt][q] = 0.f;

  issue(0);
  issue(1);

#pragma unroll 1
  for (int cn = 0; cn < NCHUNK; ++cn) {
    if (cn < NCHUNK - 2) asm volatile("cp.async.wait_group 1;" ::: "memory");
    else                 asm volatile("cp.async.wait_group 0;" ::: "memory");
    __syncthreads();
    if (cn + 2 < NCHUNK) issue(cn + 2);

    int bf = cn % 3;
    unsigned abase = aAddr[bf];
    unsigned bbase = diag ? aAddr[bf] : bAddr[bf];
#pragma unroll
    for (int ks = 0; ks < 2; ++ks) {
      unsigned afr[2][4];
#pragma unroll
      for (int mt = 0; mt < 2; ++mt)
        ldsm4(afr[mt], abase + swz(a_row + mt * 16, ks * 2 + a_chv));
      unsigned bfr[8][2];
#pragma unroll
      for (int p = 0; p < 4; ++p) {
        unsigned r4[4];
        ldsm4(r4, bbase + swz(b_row + p * 16, ks * 2 + b_chv));
        bfr[2 * p][0] = r4[0];     bfr[2 * p][1] = r4[1];
        bfr[2 * p + 1][0] = r4[2]; bfr[2 * p + 1][1] = r4[3];
      }
#pragma unroll
      for (int mt = 0; mt < 2; ++mt)
#pragma unroll
        for (int nt = 0; nt < 8; ++nt)
          mma16816(acc[mt][nt], afr[mt], bfr[nt]);
    }
  }

  // epilogue: dist -> exp -> masked accumulate
  int g = lane >> 2, qp = 2 * (lane & 3);
  float lsum = 0.f;
#pragma unroll
  for (int mt = 0; mt < 2; ++mt) {
    int ia = i0 + wm * 32 + mt * 16 + g;
    int ib = ia + 8;
    float sqa = g_sq[ia], sqb = g_sq[ib];
#pragma unroll
    for (int nt = 0; nt < 8; ++nt) {
      int jb0 = j0 + wn * 64 + nt * 8 + qp;
      float sj0 = g_sq[jb0], sj1 = g_sq[jb0 + 1];
      float d00 = fmaxf(sqa + sj0 - 2.f * acc[mt][nt][0], 0.f);
      float d01 = fmaxf(sqa + sj1 - 2.f * acc[mt][nt][1], 0.f);
      float d10 = fmaxf(sqb + sj0 - 2.f * acc[mt][nt][2], 0.f);
      float d11 = fmaxf(sqb + sj1 - 2.f * acc[mt][nt][3], 0.f);
      float e00 = __expf(-GAMMA_F * d00);
      float e01 = __expf(-GAMMA_F * d01);
      float e10 = __expf(-GAMMA_F * d10);
      float e11 = __expf(-GAMMA_F * d11);
      if (!diag) {
        lsum += (e00 + e01) + (e10 + e11);
      } else {
        if (jb0     < ia) lsum += e00;
        if (jb0 + 1 < ia) lsum += e01;
        if (jb0     < ib) lsum += e10;
        if (jb0 + 1 < ib) lsum += e11;
      }
    }
  }

  for (int off = 16; off; off >>= 1) lsum += __shfl_down_sync(0xffffffffu, lsum, off);
  if (lane == 0) red[w] = lsum;
  __syncthreads();
  if (tid == 0) {
    float s = 0.f;
#pragma unroll
    for (int k = 0; k < 8; ++k) s += red[k];
    atomicAdd(&g_acc[cls], (double)s);
    __threadfence();
    unsigned old = atomicAdd(&g_cnt, 1u);
    if (old == 527u) {
      volatile double* a = g_acc;
      double sxx = 2.0 * a[0] + (double)N_;
      double syy = 2.0 * a[2] + (double)N_;
      double sxy = a[1];
      out[0] = (float)((sxx + syy - 2.0 * sxy) / ((double)N_ * (double)N_));
    }
  }
}

extern "C" void kernel_launch(void* const* d_in, const int* in_sizes, int n_in,
                              void* d_out, int out_size) {
  const float* x = (const float*)d_in[0];
  const float* y = (const float*)d_in[1];

  zero_kernel<<<72, 512>>>();
  d2_kernel<<<1024, 128>>>(x, y);
  gather_kernel<<<1024, 128>>>(y);
  gram_mma_kernel<<<528, 256>>>((float*)d_out);
}